// round 14
// baseline (speedup 1.0000x reference)
#include <cuda_runtime.h>
#include <float.h>

#define H_IN   161
#define W_IN   161
#define C      128
#define H_OUT  641
#define W_OUT  641
#define NPIX   (H_OUT * W_OUT)
#define NEGV   (-1000000000.0f)
#define LOG2E  1.4426950408889634f

#define TPB      224     // threads = pixels per strip (strip2: 196 used)
#define CSTRIDE  132     // column stride in floats: mod 32 == 4 -> 8 quads
                         // of a warp hit 8 distinct bank groups (conflict-free)
#define NCOLSMAX 57

typedef unsigned long long ull;

#define EX2(dst, src) asm("ex2.approx.f32 %0, %1;" : "=f"(dst) : "f"(src))

__device__ __forceinline__ void f2x2_unpack(ull v, float& lo, float& hi) {
    asm("mov.b64 {%0, %1}, %2;" : "=f"(lo), "=f"(hi) : "l"(v));
}

// ---------------------------------------------------------------------------
// Single fused kernel, grid (3, 641): block = one 224-pixel strip of one row.
//  - classify phase per block (probs stays L2-resident; ~300 instrs)
//  - fill: y-lerp (log2e-prescaled) into SMEM, stride 132 (round-8 layout)
//  - fast path: thread-per-pixel, fully unrolled 128-channel pass,
//    LDS.128 at compile-time offsets, pair-max argmax, 1 EX2/channel.
// ---------------------------------------------------------------------------
__global__ void __launch_bounds__(TPB, 6)
fused_kernel(const float* __restrict__ in, const float* __restrict__ probs,
             float* __restrict__ out) {
    __shared__ float sbuf[NCOLSMAX * CSTRIDE];   // 30096 B
    __shared__ float sbias[128];
    __shared__ int   ssem[128];
    __shared__ int   smaskid[128];
    __shared__ unsigned swmask[4];
    __shared__ unsigned char sdetsh[128];
    __shared__ int   sflags;

    const int tid  = threadIdx.x;
    const int lane = tid & 31;

    // ================= CLASSIFY (once per block) =================
    if (tid < 128) {
        const float* row = probs + tid * 134;
        float best = row[0];
        int bi = 0;
        #pragma unroll 4
        for (int c = 1; c < 133; ++c) {
            float v = row[c];
            if (v > best) { best = v; bi = c; }   // strict >: first occurrence
        }
        ssem[tid]   = bi;
        sdetsh[tid] = (best >= 0.7f) ? 1 : 0;
    }
    __syncthreads();
    if (tid < 128) {
        unsigned b = __ballot_sync(0xffffffffu, sdetsh[tid] != 0);
        if (lane == 0) swmask[tid >> 5] = b;
    }
    __syncthreads();
    if (tid < 128) {
        unsigned b = swmask[tid >> 5];
        int cnt = __popc(b & (0xffffffffu >> (31 - lane)));
        for (int k = 0; k < (tid >> 5); ++k) cnt += __popc(swmask[k]);
        smaskid[tid] = cnt - 1;
        sbias[tid]   = ((b >> lane) & 1u) ? 0.0f : NEGV;
    }
    if (tid == 0) {
        int tot = __popc(swmask[0]) + __popc(swmask[1]) +
                  __popc(swmask[2]) + __popc(swmask[3]);
        sflags = ((tot > 0) ? 1 : 0) | ((tot == 128) ? 2 : 0);
    }

    // ================= GEOMETRY =================
    const int strip = blockIdx.x;                 // 0, 1, 2
    const int y     = blockIdx.y;
    const int cb    = strip * 56;                 // 0 / 56 / 112
    const int nc    = (strip == 2) ? 49 : 57;     // columns to load

    const int y0 = y >> 2;
    const int y1 = min(y0 + 1, H_IN - 1);
    const float wy = (float)(y & 3) * 0.25f;
    const float w1 = wy * LOG2E;
    const float w0 = (1.0f - wy) * LOG2E;

    // ---- fill: y-lerp (log2e-prescaled) into SMEM ----
    {
        const float4* r0 = (const float4*)(in + ((size_t)y0 * W_IN + cb) * C);
        const float4* r1 = (const float4*)(in + ((size_t)y1 * W_IN + cb) * C);
        const int nv = nc * 32;   // float4 count
        if ((y & 3) == 0) {
            #pragma unroll 4
            for (int i = tid; i < nv; i += TPB) {
                float4 a = r0[i];
                float* dst = sbuf + (i >> 5) * CSTRIDE + (i & 31) * 4;
                *(float4*)dst = make_float4(a.x * w0, a.y * w0,
                                            a.z * w0, a.w * w0);
            }
        } else {
            #pragma unroll 4
            for (int i = tid; i < nv; i += TPB) {
                float4 a = r0[i], b = r1[i];
                float* dst = sbuf + (i >> 5) * CSTRIDE + (i & 31) * 4;
                *(float4*)dst = make_float4(a.x * w0 + b.x * w1,
                                            a.y * w0 + b.y * w1,
                                            a.z * w0 + b.z * w1,
                                            a.w * w0 + b.w * w1);
            }
        }
    }
    __syncthreads();

    const int hasdet = sflags & 1;
    const int alldet = sflags & 2;

    const int px = 4 * cb + tid;                  // output x of this thread
    if (px >= W_OUT) return;

    const int x0  = px >> 2;
    const int x0r = x0 - cb;
    const int x1r = min(x0 + 1, W_IN - 1) - cb;
    const float wx   = (float)(px & 3) * 0.25f;
    const float omwx = 1.0f - wx;
    const float* base_a = sbuf + x0r * CSTRIDE;
    const float* base_b = sbuf + x1r * CSTRIDE;

    if (alldet) {
        // ================= FAST PATH =================
        // detected mask all-ones: masked == resized, detected_pixel == 1.
        float bv = -FLT_MAX;     // max over channels (log2-scaled domain)
        int   bp = 0;            // winning channel PAIR (0..63)
        float s0 = 0.f, s1 = 0.f;

        #pragma unroll
        for (int c4 = 0; c4 < 32; ++c4) {
            const int off = c4 * 4;                 // compile-time constant
            float4 A = *(const float4*)(base_a + off);
            float4 B = *(const float4*)(base_b + off);
            float v0 = fmaf(B.x, wx, A.x * omwx);
            float v1 = fmaf(B.y, wx, A.y * omwx);
            float v2 = fmaf(B.z, wx, A.z * omwx);
            float v3 = fmaf(B.w, wx, A.w * omwx);
            // pair maxes; strict > keeps earliest pair on ties
            float m01 = fmaxf(v0, v1);
            float m23 = fmaxf(v2, v3);
            const int pi = c4 * 2;
            if (m01 > bv) { bv = m01; bp = pi; }
            if (m23 > bv) { bv = m23; bp = pi + 1; }
            float e0, e1, e2, e3;
            EX2(e0, v0); EX2(e1, v1); EX2(e2, v2); EX2(e3, v3);
            s0 += e0; s1 += e1; s0 += e2; s1 += e3;
        }

        // epilogue: resolve within-pair index (bit-identical recompute)
        const int eoff = 2 * bp;
        float a0 = base_a[eoff], b0 = base_b[eoff];
        float v0 = fmaf(b0, wx, a0 * omwx);
        const int bi = 2 * bp + ((v0 == bv) ? 0 : 1);   // first occurrence

        const float s = s0 + s1;
        float eb; EX2(eb, bv);
        // pixel_conf > 0.4  <=>  s < 2.5 * 2^bv   (detected_pixel == 1)
        const float cf = (s < 2.5f * eb) ? 1.0f : 0.0f;

        const int semI = ssem[bi];
        const int p = y * W_OUT + px;
        out[p]            = (float)(smaskid[bi] + 1);
        out[NPIX + p]     = (float)semI;
        out[2 * NPIX + p] = (semI < 80)  ? cf : 0.0f;
        out[3 * NPIX + p] = (semI >= 80) ? cf : 0.0f;
    } else {
        // ================= GENERAL PATH (rare) =================
        float fm = -FLT_MAX, bv = -FLT_MAX, s = 0.0f;
        int bi = 0;
        const ull* pa = (const ull*)base_a;
        const ull* pb = (const ull*)base_b;
        const ull* pg = (const ull*)sbias;
        #pragma unroll 8
        for (int c2 = 0; c2 < 64; ++c2) {
            float a0, a1, b0, b1, gg0, gg1;
            f2x2_unpack(pa[c2], a0, a1);
            f2x2_unpack(pb[c2], b0, b1);
            f2x2_unpack(pg[c2], gg0, gg1);
            {
                float v = a0 * omwx + b0 * wx;
                fm = fmaxf(fm, v);
                float mv = v + gg0;
                if (mv > bv) { bv = mv; bi = 2 * c2; }
                float e; EX2(e, mv); s += e;
            }
            {
                float v = a1 * omwx + b1 * wx;
                fm = fmaxf(fm, v);
                float mv = v + gg1;
                if (mv > bv) { bv = mv; bi = 2 * c2 + 1; }
                float e; EX2(e, mv); s += e;
            }
        }
        float eb; EX2(eb, bv);
        const float cf = (s < 2.5f * eb && fm == bv) ? 1.0f : 0.0f;

        float maskid, sem, thing, stuff;
        if (hasdet) {
            const int semI = ssem[bi];
            maskid = (float)(smaskid[bi] + 1);
            sem    = (float)semI;
            thing  = (semI < 80)  ? cf : 0.0f;
            stuff  = (semI >= 80) ? cf : 0.0f;
        } else {
            maskid = 1.0f; sem = 0.0f; thing = 0.0f; stuff = 0.0f;
        }
        const int p = y * W_OUT + px;
        out[p]            = maskid;
        out[NPIX + p]     = sem;
        out[2 * NPIX + p] = thing;
        out[3 * NPIX + p] = stuff;
    }
}

// ---------------------------------------------------------------------------
extern "C" void kernel_launch(void* const* d_in, const int* in_sizes, int n_in,
                              void* d_out, int out_size) {
    const float* logits = (const float*)d_in[0];  // (161,161,128)
    const float* probs  = (const float*)d_in[1];  // (128,134)
    if (n_in >= 2 && in_sizes[0] < in_sizes[1]) { // safety: order by size
        const float* t = logits; logits = probs; probs = t;
    }
    float* out = (float*)d_out;

    static int inited = 0;
    if (!inited) {
        cudaFuncSetAttribute(fused_kernel,
                             cudaFuncAttributePreferredSharedMemoryCarveout, 100);
        inited = 1;
    }

    fused_kernel<<<dim3(3, H_OUT), TPB>>>(logits, probs, out);
}

// round 15
// speedup vs baseline: 2.6899x; 2.6899x over previous
#include <cuda_runtime.h>
#include <float.h>

#define H_IN   161
#define W_IN   161
#define C      128
#define H_OUT  641
#define W_OUT  641
#define NPIX   (H_OUT * W_OUT)
#define NEGV   (-1000000000.0f)
#define LOG2E  1.4426950408889634f

#define TPB      224     // threads = pixels per strip (strip2: 193 used)
#define CSTRIDE  132     // column stride in floats: mod 32 == 4 -> 8 quads
                         // of a warp hit 8 distinct bank groups (conflict-free)
#define NCOLSMAX 57

typedef unsigned long long ull;

// Per-slot classification results (phase A -> phase B)
__device__ int      g_maskid[128];
__device__ int      g_sem[128];
__device__ unsigned g_detmask[4];
__device__ int      g_flags;     // bit0 = hasdet, bit1 = alldet

#define EX2(dst, src) asm("ex2.approx.f32 %0, %1;" : "=f"(dst) : "f"(src))

__device__ __forceinline__ void f2x2_unpack(ull v, float& lo, float& hi) {
    asm("mov.b64 {%0, %1}, %2;" : "=f"(lo), "=f"(hi) : "l"(v));
}

// ---------------------------------------------------------------------------
// Phase A: 1 block, 1024 threads. Warp-per-slot, fully coalesced:
// warp w handles slots 4w..4w+3; lanes read row[32k+lane] (5 loads/slot),
// shfl-argmax with min-index tiebreak (== first occurrence).
// ---------------------------------------------------------------------------
__global__ void classify_kernel(const float* __restrict__ probs /*128x134*/) {
    __shared__ unsigned char sdet[128];
    __shared__ unsigned wmask[4];

    const int t    = threadIdx.x;
    const int lane = t & 31;
    const int w    = t >> 5;               // warp 0..31

    #pragma unroll
    for (int j = 0; j < 4; ++j) {
        const int s = 4 * w + j;
        const float* row = probs + s * 134;
        float best = -FLT_MAX;
        int   bi   = 0;
        #pragma unroll
        for (int k = 0; k < 5; ++k) {
            const int c = 32 * k + lane;
            if (c < 133) {
                float v = row[c];
                if (v > best) { best = v; bi = c; }
            }
        }
        // warp argmax, min-index on ties -> first occurrence overall
        #pragma unroll
        for (int off = 16; off >= 1; off >>= 1) {
            float ob  = __shfl_xor_sync(0xffffffffu, best, off);
            int   obi = __shfl_xor_sync(0xffffffffu, bi,   off);
            if (ob > best || (ob == best && obi < bi)) { best = ob; bi = obi; }
        }
        if (lane == 0) {
            g_sem[s] = bi;
            sdet[s]  = (best >= 0.7f) ? 1 : 0;
        }
    }
    __syncthreads();

    if (t < 128) {
        unsigned b = __ballot_sync(0xffffffffu, sdet[t] != 0);
        if (lane == 0) wmask[t >> 5] = b;
    }
    __syncthreads();
    if (t < 128) {
        unsigned b = wmask[t >> 5];
        int cnt = __popc(b & (0xffffffffu >> (31 - lane)));
        for (int k = 0; k < (t >> 5); ++k) cnt += __popc(wmask[k]);
        g_maskid[t] = cnt - 1;
        if (t == 0) {
            int tot = __popc(wmask[0]) + __popc(wmask[1]) +
                      __popc(wmask[2]) + __popc(wmask[3]);
            g_detmask[0] = wmask[0]; g_detmask[1] = wmask[1];
            g_detmask[2] = wmask[2]; g_detmask[3] = wmask[3];
            g_flags = ((tot > 0) ? 1 : 0) | ((tot == 128) ? 2 : 0);
        }
    }
}

// ---------------------------------------------------------------------------
// Phase B: grid (3, 641): block = one 224-pixel strip of one row.
//  - fill: y-lerp (log2e-prescaled) into SMEM, stride 132 (conflict-free)
//  - fast path: thread-per-pixel, fully unrolled 128-channel pass,
//    LDS.128 at compile-time offsets, pair-max argmax, 1 EX2/channel.
// ---------------------------------------------------------------------------
__global__ void __launch_bounds__(TPB, 6)
postproc_kernel(const float* __restrict__ in, float* __restrict__ out) {
    __shared__ float sbuf[NCOLSMAX * CSTRIDE];   // 30096 B
    __shared__ float sbias[128];
    __shared__ int   ssem[128];
    __shared__ int   smaskid[128];

    const int tid = threadIdx.x;

    // ================= GEOMETRY =================
    const int strip = blockIdx.x;                 // 0, 1, 2
    const int y     = blockIdx.y;
    const int cb    = strip * 56;                 // 0 / 56 / 112
    const int nc    = (strip == 2) ? 49 : 57;     // columns to load

    const int y0 = y >> 2;
    const int y1 = min(y0 + 1, H_IN - 1);
    const float wy = (float)(y & 3) * 0.25f;
    const float w1 = wy * LOG2E;
    const float w0 = (1.0f - wy) * LOG2E;

    // ---- fill: y-lerp (log2e-prescaled) into SMEM ----
    {
        const float4* r0 = (const float4*)(in + ((size_t)y0 * W_IN + cb) * C);
        const float4* r1 = (const float4*)(in + ((size_t)y1 * W_IN + cb) * C);
        const int nv = nc * 32;   // float4 count
        if ((y & 3) == 0) {
            #pragma unroll 4
            for (int i = tid; i < nv; i += TPB) {
                float4 a = r0[i];
                float* dst = sbuf + (i >> 5) * CSTRIDE + (i & 31) * 4;
                *(float4*)dst = make_float4(a.x * w0, a.y * w0,
                                            a.z * w0, a.w * w0);
            }
        } else {
            #pragma unroll 4
            for (int i = tid; i < nv; i += TPB) {
                float4 a = r0[i], b = r1[i];
                float* dst = sbuf + (i >> 5) * CSTRIDE + (i & 31) * 4;
                *(float4*)dst = make_float4(a.x * w0 + b.x * w1,
                                            a.y * w0 + b.y * w1,
                                            a.z * w0 + b.z * w1,
                                            a.w * w0 + b.w * w1);
            }
        }
        if (tid < 128) {
            unsigned m = g_detmask[tid >> 5];
            sbias[tid]   = ((m >> (tid & 31)) & 1u) ? 0.0f : NEGV;
            ssem[tid]    = g_sem[tid];
            smaskid[tid] = g_maskid[tid];
        }
    }
    __syncthreads();

    const int flags  = g_flags;
    const int hasdet = flags & 1;
    const int alldet = flags & 2;

    const int px = 4 * cb + tid;                  // output x of this thread
    if (px >= W_OUT) return;

    const int x0  = px >> 2;
    const int x0r = x0 - cb;
    const int x1r = min(x0 + 1, W_IN - 1) - cb;
    const float wx   = (float)(px & 3) * 0.25f;
    const float omwx = 1.0f - wx;
    const float* base_a = sbuf + x0r * CSTRIDE;
    const float* base_b = sbuf + x1r * CSTRIDE;

    if (alldet) {
        // ================= FAST PATH =================
        // detected mask all-ones: masked == resized, detected_pixel == 1.
        float bv = -FLT_MAX;     // max over channels (log2-scaled domain)
        int   bp = 0;            // winning channel PAIR (0..63)
        float s0 = 0.f, s1 = 0.f;

        #pragma unroll
        for (int c4 = 0; c4 < 32; ++c4) {
            const int off = c4 * 4;                 // compile-time constant
            float4 A = *(const float4*)(base_a + off);
            float4 B = *(const float4*)(base_b + off);
            float v0 = fmaf(B.x, wx, A.x * omwx);
            float v1 = fmaf(B.y, wx, A.y * omwx);
            float v2 = fmaf(B.z, wx, A.z * omwx);
            float v3 = fmaf(B.w, wx, A.w * omwx);
            // pair maxes; strict > keeps earliest pair on ties
            float m01 = fmaxf(v0, v1);
            float m23 = fmaxf(v2, v3);
            const int pi = c4 * 2;
            if (m01 > bv) { bv = m01; bp = pi; }
            if (m23 > bv) { bv = m23; bp = pi + 1; }
            float e0, e1, e2, e3;
            EX2(e0, v0); EX2(e1, v1); EX2(e2, v2); EX2(e3, v3);
            s0 += e0; s1 += e1; s0 += e2; s1 += e3;
        }

        // epilogue: resolve within-pair index (bit-identical recompute)
        const int eoff = 2 * bp;
        float a0 = base_a[eoff], b0 = base_b[eoff];
        float v0 = fmaf(b0, wx, a0 * omwx);
        const int bi = 2 * bp + ((v0 == bv) ? 0 : 1);   // first occurrence

        const float s = s0 + s1;
        float eb; EX2(eb, bv);
        // pixel_conf > 0.4  <=>  s < 2.5 * 2^bv   (detected_pixel == 1)
        const float cf = (s < 2.5f * eb) ? 1.0f : 0.0f;

        const int semI = ssem[bi];
        const int p = y * W_OUT + px;
        out[p]            = (float)(smaskid[bi] + 1);
        out[NPIX + p]     = (float)semI;
        out[2 * NPIX + p] = (semI < 80)  ? cf : 0.0f;
        out[3 * NPIX + p] = (semI >= 80) ? cf : 0.0f;
    } else {
        // ================= GENERAL PATH (rare) =================
        float fm = -FLT_MAX, bv = -FLT_MAX, s = 0.0f;
        int bi = 0;
        const ull* pa = (const ull*)base_a;
        const ull* pb = (const ull*)base_b;
        const ull* pg = (const ull*)sbias;
        #pragma unroll 8
        for (int c2 = 0; c2 < 64; ++c2) {
            float a0, a1, b0, b1, gg0, gg1;
            f2x2_unpack(pa[c2], a0, a1);
            f2x2_unpack(pb[c2], b0, b1);
            f2x2_unpack(pg[c2], gg0, gg1);
            {
                float v = a0 * omwx + b0 * wx;
                fm = fmaxf(fm, v);
                float mv = v + gg0;
                if (mv > bv) { bv = mv; bi = 2 * c2; }
                float e; EX2(e, mv); s += e;
            }
            {
                float v = a1 * omwx + b1 * wx;
                fm = fmaxf(fm, v);
                float mv = v + gg1;
                if (mv > bv) { bv = mv; bi = 2 * c2 + 1; }
                float e; EX2(e, mv); s += e;
            }
        }
        float eb; EX2(eb, bv);
        const float cf = (s < 2.5f * eb && fm == bv) ? 1.0f : 0.0f;

        float maskid, sem, thing, stuff;
        if (hasdet) {
            const int semI = ssem[bi];
            maskid = (float)(smaskid[bi] + 1);
            sem    = (float)semI;
            thing  = (semI < 80)  ? cf : 0.0f;
            stuff  = (semI >= 80) ? cf : 0.0f;
        } else {
            maskid = 1.0f; sem = 0.0f; thing = 0.0f; stuff = 0.0f;
        }
        const int p = y * W_OUT + px;
        out[p]            = maskid;
        out[NPIX + p]     = sem;
        out[2 * NPIX + p] = thing;
        out[3 * NPIX + p] = stuff;
    }
}

// ---------------------------------------------------------------------------
extern "C" void kernel_launch(void* const* d_in, const int* in_sizes, int n_in,
                              void* d_out, int out_size) {
    const float* logits = (const float*)d_in[0];  // (161,161,128)
    const float* probs  = (const float*)d_in[1];  // (128,134)
    if (n_in >= 2 && in_sizes[0] < in_sizes[1]) { // safety: order by size
        const float* t = logits; logits = probs; probs = t;
    }
    float* out = (float*)d_out;

    static int inited = 0;
    if (!inited) {
        cudaFuncSetAttribute(postproc_kernel,
                             cudaFuncAttributePreferredSharedMemoryCarveout, 100);
        inited = 1;
    }

    classify_kernel<<<1, 1024>>>(probs);
    postproc_kernel<<<dim3(3, H_OUT), TPB>>>(logits, out);
}

// round 16
// speedup vs baseline: 3.0431x; 1.1313x over previous
#include <cuda_runtime.h>
#include <float.h>

#define H_IN   161
#define W_IN   161
#define C      128
#define H_OUT  641
#define W_OUT  641
#define NPIX   (H_OUT * W_OUT)
#define NEGV   (-1000000000.0f)
#define LOG2E  1.4426950408889634f

#define TPB      224     // threads = pixels per strip (strip2: 193 used)
#define CSTRIDE  132     // column stride in floats: mod 32 == 4 -> 8 quads
                         // of a warp hit 8 distinct bank groups (conflict-free)
#define NCOLSMAX 57

typedef unsigned long long ull;

// Per-slot classification results (phase A -> phase B)
__device__ int      g_maskid[128];
__device__ int      g_sem[128];
__device__ unsigned g_detmask[4];
__device__ int      g_flags;     // bit0 = hasdet, bit1 = alldet

#define EX2(dst, src) asm("ex2.approx.f32 %0, %1;" : "=f"(dst) : "f"(src))

__device__ __forceinline__ void f2x2_unpack(ull v, float& lo, float& hi) {
    asm("mov.b64 {%0, %1}, %2;" : "=f"(lo), "=f"(hi) : "l"(v));
}

// ---------------------------------------------------------------------------
// Phase A: 1 block, 1024 threads. Warp-per-slot, fully coalesced:
// warp w handles slots 4w..4w+3; lanes read row[32k+lane] (5 loads/slot),
// shfl-argmax with min-index tiebreak (== first occurrence).
// ---------------------------------------------------------------------------
__global__ void classify_kernel(const float* __restrict__ probs /*128x134*/) {
    __shared__ unsigned char sdet[128];
    __shared__ unsigned wmask[4];

    const int t    = threadIdx.x;
    const int lane = t & 31;
    const int w    = t >> 5;               // warp 0..31

    #pragma unroll
    for (int j = 0; j < 4; ++j) {
        const int s = 4 * w + j;
        const float* row = probs + s * 134;
        float best = -FLT_MAX;
        int   bi   = 0;
        #pragma unroll
        for (int k = 0; k < 5; ++k) {
            const int c = 32 * k + lane;
            if (c < 133) {
                float v = row[c];
                if (v > best) { best = v; bi = c; }
            }
        }
        // warp argmax, min-index on ties -> first occurrence overall
        #pragma unroll
        for (int off = 16; off >= 1; off >>= 1) {
            float ob  = __shfl_xor_sync(0xffffffffu, best, off);
            int   obi = __shfl_xor_sync(0xffffffffu, bi,   off);
            if (ob > best || (ob == best && obi < bi)) { best = ob; bi = obi; }
        }
        if (lane == 0) {
            g_sem[s] = bi;
            sdet[s]  = (best >= 0.7f) ? 1 : 0;
        }
    }
    __syncthreads();

    if (t < 128) {
        unsigned b = __ballot_sync(0xffffffffu, sdet[t] != 0);
        if (lane == 0) wmask[t >> 5] = b;
    }
    __syncthreads();
    if (t < 128) {
        unsigned b = wmask[t >> 5];
        int cnt = __popc(b & (0xffffffffu >> (31 - lane)));
        for (int k = 0; k < (t >> 5); ++k) cnt += __popc(wmask[k]);
        g_maskid[t] = cnt - 1;
        if (t == 0) {
            int tot = __popc(wmask[0]) + __popc(wmask[1]) +
                      __popc(wmask[2]) + __popc(wmask[3]);
            g_detmask[0] = wmask[0]; g_detmask[1] = wmask[1];
            g_detmask[2] = wmask[2]; g_detmask[3] = wmask[3];
            g_flags = ((tot > 0) ? 1 : 0) | ((tot == 128) ? 2 : 0);
        }
    }
}

// ---------------------------------------------------------------------------
// Phase B: grid (3, 641): block = one 224-pixel strip of one row.
//  - fill: y-lerp (log2e-prescaled) into SMEM, stride 132 (conflict-free)
//  - fast path: thread-per-pixel, fully unrolled 128-channel pass,
//    LDS.128 at compile-time offsets, pair-max argmax, 1 EX2/channel.
// NOTE: no shared-carveout override -- L1D must stay large so the ~8x
// cross-block reuse of input rows hits L1 (the round-15 regression).
// ---------------------------------------------------------------------------
__global__ void __launch_bounds__(TPB, 4)
postproc_kernel(const float* __restrict__ in, float* __restrict__ out) {
    __shared__ float sbuf[NCOLSMAX * CSTRIDE];   // 30096 B
    __shared__ float sbias[128];
    __shared__ int   ssem[128];
    __shared__ int   smaskid[128];

    const int tid = threadIdx.x;

    // ================= GEOMETRY =================
    const int strip = blockIdx.x;                 // 0, 1, 2
    const int y     = blockIdx.y;
    const int cb    = strip * 56;                 // 0 / 56 / 112
    const int nc    = (strip == 2) ? 49 : 57;     // columns to load

    const int y0 = y >> 2;
    const int y1 = min(y0 + 1, H_IN - 1);
    const float wy = (float)(y & 3) * 0.25f;
    const float w1 = wy * LOG2E;
    const float w0 = (1.0f - wy) * LOG2E;

    // ---- fill: y-lerp (log2e-prescaled) into SMEM ----
    {
        const float4* r0 = (const float4*)(in + ((size_t)y0 * W_IN + cb) * C);
        const float4* r1 = (const float4*)(in + ((size_t)y1 * W_IN + cb) * C);
        const int nv = nc * 32;   // float4 count
        if ((y & 3) == 0) {
            #pragma unroll 4
            for (int i = tid; i < nv; i += TPB) {
                float4 a = r0[i];
                float* dst = sbuf + (i >> 5) * CSTRIDE + (i & 31) * 4;
                *(float4*)dst = make_float4(a.x * w0, a.y * w0,
                                            a.z * w0, a.w * w0);
            }
        } else {
            #pragma unroll 4
            for (int i = tid; i < nv; i += TPB) {
                float4 a = r0[i], b = r1[i];
                float* dst = sbuf + (i >> 5) * CSTRIDE + (i & 31) * 4;
                *(float4*)dst = make_float4(a.x * w0 + b.x * w1,
                                            a.y * w0 + b.y * w1,
                                            a.z * w0 + b.z * w1,
                                            a.w * w0 + b.w * w1);
            }
        }
        if (tid < 128) {
            unsigned m = g_detmask[tid >> 5];
            sbias[tid]   = ((m >> (tid & 31)) & 1u) ? 0.0f : NEGV;
            ssem[tid]    = g_sem[tid];
            smaskid[tid] = g_maskid[tid];
        }
    }
    __syncthreads();

    const int flags  = g_flags;
    const int hasdet = flags & 1;
    const int alldet = flags & 2;

    const int px = 4 * cb + tid;                  // output x of this thread
    if (px >= W_OUT) return;

    const int x0  = px >> 2;
    const int x0r = x0 - cb;
    const int x1r = min(x0 + 1, W_IN - 1) - cb;
    const float wx   = (float)(px & 3) * 0.25f;
    const float omwx = 1.0f - wx;
    const float* base_a = sbuf + x0r * CSTRIDE;
    const float* base_b = sbuf + x1r * CSTRIDE;

    if (alldet) {
        // ================= FAST PATH =================
        // detected mask all-ones: masked == resized, detected_pixel == 1.
        float bv = -FLT_MAX;     // max over channels (log2-scaled domain)
        int   bp = 0;            // winning channel PAIR (0..63)
        float s0 = 0.f, s1 = 0.f;

        #pragma unroll
        for (int c4 = 0; c4 < 32; ++c4) {
            const int off = c4 * 4;                 // compile-time constant
            float4 A = *(const float4*)(base_a + off);
            float4 B = *(const float4*)(base_b + off);
            float v0 = fmaf(B.x, wx, A.x * omwx);
            float v1 = fmaf(B.y, wx, A.y * omwx);
            float v2 = fmaf(B.z, wx, A.z * omwx);
            float v3 = fmaf(B.w, wx, A.w * omwx);
            // pair maxes; strict > keeps earliest pair on ties
            float m01 = fmaxf(v0, v1);
            float m23 = fmaxf(v2, v3);
            const int pi = c4 * 2;
            if (m01 > bv) { bv = m01; bp = pi; }
            if (m23 > bv) { bv = m23; bp = pi + 1; }
            float e0, e1, e2, e3;
            EX2(e0, v0); EX2(e1, v1); EX2(e2, v2); EX2(e3, v3);
            s0 += e0; s1 += e1; s0 += e2; s1 += e3;
        }

        // epilogue: resolve within-pair index (bit-identical recompute)
        const int eoff = 2 * bp;
        float a0 = base_a[eoff], b0 = base_b[eoff];
        float v0 = fmaf(b0, wx, a0 * omwx);
        const int bi = 2 * bp + ((v0 == bv) ? 0 : 1);   // first occurrence

        const float s = s0 + s1;
        float eb; EX2(eb, bv);
        // pixel_conf > 0.4  <=>  s < 2.5 * 2^bv   (detected_pixel == 1)
        const float cf = (s < 2.5f * eb) ? 1.0f : 0.0f;

        const int semI = ssem[bi];
        const int p = y * W_OUT + px;
        out[p]            = (float)(smaskid[bi] + 1);
        out[NPIX + p]     = (float)semI;
        out[2 * NPIX + p] = (semI < 80)  ? cf : 0.0f;
        out[3 * NPIX + p] = (semI >= 80) ? cf : 0.0f;
    } else {
        // ================= GENERAL PATH (rare) =================
        float fm = -FLT_MAX, bv = -FLT_MAX, s = 0.0f;
        int bi = 0;
        const ull* pa = (const ull*)base_a;
        const ull* pb = (const ull*)base_b;
        const ull* pg = (const ull*)sbias;
        #pragma unroll 8
        for (int c2 = 0; c2 < 64; ++c2) {
            float a0, a1, b0, b1, gg0, gg1;
            f2x2_unpack(pa[c2], a0, a1);
            f2x2_unpack(pb[c2], b0, b1);
            f2x2_unpack(pg[c2], gg0, gg1);
            {
                float v = a0 * omwx + b0 * wx;
                fm = fmaxf(fm, v);
                float mv = v + gg0;
                if (mv > bv) { bv = mv; bi = 2 * c2; }
                float e; EX2(e, mv); s += e;
            }
            {
                float v = a1 * omwx + b1 * wx;
                fm = fmaxf(fm, v);
                float mv = v + gg1;
                if (mv > bv) { bv = mv; bi = 2 * c2 + 1; }
                float e; EX2(e, mv); s += e;
            }
        }
        float eb; EX2(eb, bv);
        const float cf = (s < 2.5f * eb && fm == bv) ? 1.0f : 0.0f;

        float maskid, sem, thing, stuff;
        if (hasdet) {
            const int semI = ssem[bi];
            maskid = (float)(smaskid[bi] + 1);
            sem    = (float)semI;
            thing  = (semI < 80)  ? cf : 0.0f;
            stuff  = (semI >= 80) ? cf : 0.0f;
        } else {
            maskid = 1.0f; sem = 0.0f; thing = 0.0f; stuff = 0.0f;
        }
        const int p = y * W_OUT + px;
        out[p]            = maskid;
        out[NPIX + p]     = sem;
        out[2 * NPIX + p] = thing;
        out[3 * NPIX + p] = stuff;
    }
}

// ---------------------------------------------------------------------------
extern "C" void kernel_launch(void* const* d_in, const int* in_sizes, int n_in,
                              void* d_out, int out_size) {
    const float* logits = (const float*)d_in[0];  // (161,161,128)
    const float* probs  = (const float*)d_in[1];  // (128,134)
    if (n_in >= 2 && in_sizes[0] < in_sizes[1]) { // safety: order by size
        const float* t = logits; logits = probs; probs = t;
    }
    float* out = (float*)d_out;

    classify_kernel<<<1, 1024>>>(probs);
    postproc_kernel<<<dim3(3, H_OUT), TPB>>>(logits, out);
}

// round 17
// speedup vs baseline: 3.5030x; 1.1511x over previous
#include <cuda_runtime.h>
#include <float.h>

#define H_IN   161
#define W_IN   161
#define C      128
#define H_OUT  641
#define W_OUT  641
#define NPIX   (H_OUT * W_OUT)
#define NEGV   (-1000000000.0f)
#define LOG2E  1.4426950408889634f

#define NCOLS   65
#define STRIDE  132       // mod 32 == 4 -> 8 pixel-quads per warp hit 8
                          // distinct bank groups (conflict-free, round-8 proven)

typedef unsigned long long ull;

// Per-slot classification results (phase A -> phase B)
__device__ int      g_maskid[128];
__device__ int      g_sem[128];
__device__ unsigned g_detmask[4];
__device__ int      g_flags;     // bit0 = hasdet, bit1 = alldet

#define EX2(dst, src) asm("ex2.approx.f32 %0, %1;" : "=f"(dst) : "f"(src))

// ---------------------------------------------------------------------------
// Packed f32x2 helpers (round-8 datapath)
// ---------------------------------------------------------------------------
__device__ __forceinline__ ull f2x2_mul(ull a, ull b) {
    ull r; asm("mul.rn.f32x2 %0, %1, %2;" : "=l"(r) : "l"(a), "l"(b)); return r;
}
__device__ __forceinline__ ull f2x2_fma(ull a, ull b, ull c) {
    ull r; asm("fma.rn.f32x2 %0, %1, %2, %3;" : "=l"(r) : "l"(a), "l"(b), "l"(c)); return r;
}
__device__ __forceinline__ ull f2x2_pack(float lo, float hi) {
    ull r; asm("mov.b64 %0, {%1, %2};" : "=l"(r) : "f"(lo), "f"(hi)); return r;
}
__device__ __forceinline__ void f2x2_unpack(ull v, float& lo, float& hi) {
    asm("mov.b64 {%0, %1}, %2;" : "=f"(lo), "=f"(hi) : "l"(v));
}

// ---------------------------------------------------------------------------
// Phase A: 1 block, 1024 threads. Warp-per-slot, fully coalesced:
// warp w handles slots 4w..4w+3; lanes read row[32k+lane] (5 loads/slot),
// shfl-argmax with min-index tiebreak (== first occurrence).
// ---------------------------------------------------------------------------
__global__ void classify_kernel(const float* __restrict__ probs /*128x134*/) {
    __shared__ unsigned char sdet[128];
    __shared__ unsigned wmask[4];

    const int t    = threadIdx.x;
    const int lane = t & 31;
    const int w    = t >> 5;               // warp 0..31

    #pragma unroll
    for (int j = 0; j < 4; ++j) {
        const int s = 4 * w + j;
        const float* row = probs + s * 134;
        float best = -FLT_MAX;
        int   bi   = 0;
        #pragma unroll
        for (int k = 0; k < 5; ++k) {
            const int c = 32 * k + lane;
            if (c < 133) {
                float v = row[c];
                if (v > best) { best = v; bi = c; }
            }
        }
        #pragma unroll
        for (int off = 16; off >= 1; off >>= 1) {
            float ob  = __shfl_xor_sync(0xffffffffu, best, off);
            int   obi = __shfl_xor_sync(0xffffffffu, bi,   off);
            if (ob > best || (ob == best && obi < bi)) { best = ob; bi = obi; }
        }
        if (lane == 0) {
            g_sem[s] = bi;
            sdet[s]  = (best >= 0.7f) ? 1 : 0;
        }
    }
    __syncthreads();

    if (t < 128) {
        unsigned b = __ballot_sync(0xffffffffu, sdet[t] != 0);
        if (lane == 0) wmask[t >> 5] = b;
    }
    __syncthreads();
    if (t < 128) {
        unsigned b = wmask[t >> 5];
        int cnt = __popc(b & (0xffffffffu >> (31 - lane)));
        for (int k = 0; k < (t >> 5); ++k) cnt += __popc(wmask[k]);
        g_maskid[t] = cnt - 1;
        if (t == 0) {
            int tot = __popc(wmask[0]) + __popc(wmask[1]) +
                      __popc(wmask[2]) + __popc(wmask[3]);
            g_detmask[0] = wmask[0]; g_detmask[1] = wmask[1];
            g_detmask[2] = wmask[2]; g_detmask[3] = wmask[3];
            g_flags = ((tot > 0) ? 1 : 0) | ((tot == 128) ? 2 : 0);
        }
    }
}

// ---------------------------------------------------------------------------
// Phase B (round-8 kernel, measured 24.35us): grid (3, 641), 256 threads.
// Block = one 256-pixel strip (strips 64/64/33 input columns).
// Fill: y-lerp (log2e-prescaled) into SMEM, stride 132 (conflict-free).
// Fast path: thread-per-pixel, packed f32x2 lerp, v-domain group max
// (4-channel groups) + bit-identical epilogue re-scan, 1 EX2/channel.
// No shared-carveout override (L1D must stay large: round-15 lesson).
// ---------------------------------------------------------------------------
__global__ void __launch_bounds__(256, 4)
postproc_kernel(const float* __restrict__ in, float* __restrict__ out) {
    __shared__ float sbuf[NCOLS * STRIDE];   // 34320 B
    __shared__ float sbias[128];
    __shared__ int   ssem[128];
    __shared__ int   smaskid[128];

    const int y  = blockIdx.y;
    const int y0 = y >> 2;
    const int y1 = min(y0 + 1, H_IN - 1);
    const float wy = (float)(y & 3) * 0.25f;
    const float w1 = wy * LOG2E;
    const float w0 = (1.0f - wy) * LOG2E;

    const int cb = blockIdx.x * 64;            // 0 / 64 / 128
    const int nc = min(NCOLS, W_IN - cb);      // 65 / 65 / 33

    // ---- fill: y-lerp (log2e-prescaled) into SMEM ----
    {
        const float4* r0 = (const float4*)(in + ((size_t)y0 * W_IN + cb) * C);
        const float4* r1 = (const float4*)(in + ((size_t)y1 * W_IN + cb) * C);
        const int nv = nc * 32;                // float4s
        if ((y & 3) == 0) {
            #pragma unroll 4
            for (int i = threadIdx.x; i < nv; i += 256) {
                float4 a = r0[i];
                float* dst = sbuf + (i >> 5) * STRIDE + (i & 31) * 4;
                *(float4*)dst = make_float4(a.x * w0, a.y * w0,
                                            a.z * w0, a.w * w0);
            }
        } else {
            #pragma unroll 4
            for (int i = threadIdx.x; i < nv; i += 256) {
                float4 a = r0[i], b = r1[i];
                float* dst = sbuf + (i >> 5) * STRIDE + (i & 31) * 4;
                *(float4*)dst = make_float4(a.x * w0 + b.x * w1,
                                            a.y * w0 + b.y * w1,
                                            a.z * w0 + b.z * w1,
                                            a.w * w0 + b.w * w1);
            }
        }
        if (threadIdx.x < 128) {
            unsigned m = g_detmask[threadIdx.x >> 5];
            sbias[threadIdx.x]   = ((m >> (threadIdx.x & 31)) & 1u) ? 0.0f : NEGV;
            ssem[threadIdx.x]    = g_sem[threadIdx.x];
            smaskid[threadIdx.x] = g_maskid[threadIdx.x];
        }
    }
    __syncthreads();

    const int flags  = g_flags;
    const int hasdet = flags & 1;
    const int alldet = flags & 2;

    const int px = cb * 4 + threadIdx.x;       // output x of this thread
    if (px >= W_OUT) return;

    const int x0 = px >> 2;
    const int x1 = min(x0 + 1, W_IN - 1);
    const float wx   = (float)(px & 3) * 0.25f;
    const float omwx = 1.0f - wx;

    if (alldet) {
        // ---------------- FAST PATH (round-8 verbatim) ----------------
        // masked == resized, full_max == det_max, detected_pixel == 1.
        const ull* pa = (const ull*)(sbuf + (x0 - cb) * STRIDE);
        const ull* pb = (const ull*)(sbuf + (x1 - cb) * STRIDE);
        const ull wx2   = f2x2_pack(wx, wx);
        const ull omwx2 = f2x2_pack(omwx, omwx);

        float bv = -FLT_MAX;
        int   bg = 0;
        float s0 = 0.0f, s1 = 0.0f;

        #pragma unroll
        for (int g = 0; g < 32; ++g) {
            ull A01 = pa[2 * g];
            ull A23 = pa[2 * g + 1];
            ull B01 = pb[2 * g];
            ull B23 = pb[2 * g + 1];
            ull v01 = f2x2_fma(B01, wx2, f2x2_mul(A01, omwx2));
            ull v23 = f2x2_fma(B23, wx2, f2x2_mul(A23, omwx2));
            float v0, v1, v2, v3;
            f2x2_unpack(v01, v0, v1);
            f2x2_unpack(v23, v2, v3);
            float gm = fmaxf(fmaxf(v0, v1), fmaxf(v2, v3));
            bool t = (gm > bv);          // strict >: keeps earliest group on ties
            bv = t ? gm : bv;
            bg = t ? g  : bg;
            float e0, e1, e2, e3;
            EX2(e0, v0); EX2(e1, v1); EX2(e2, v2); EX2(e3, v3);
            s0 += e0; s1 += e1; s0 += e2; s1 += e3;
        }
        const float s = s0 + s1;

        // epilogue: recover within-group index (first occurrence, identical FP ops)
        int bi;
        {
            ull A01 = pa[2 * bg];
            ull A23 = pa[2 * bg + 1];
            ull B01 = pb[2 * bg];
            ull B23 = pb[2 * bg + 1];
            ull v01 = f2x2_fma(B01, wx2, f2x2_mul(A01, omwx2));
            ull v23 = f2x2_fma(B23, wx2, f2x2_mul(A23, omwx2));
            float v0, v1, v2, v3;
            f2x2_unpack(v01, v0, v1);
            f2x2_unpack(v23, v2, v3);
            int r = 3;
            if (v2 == bv) r = 2;
            if (v1 == bv) r = 1;
            if (v0 == bv) r = 0;
            bi = 4 * bg + r;
        }

        // pixel_conf > 0.4  <=>  s < 2.5 * 2^bv   (detected_pixel == 1)
        float eb; EX2(eb, bv);
        const float cf = (s < 2.5f * eb) ? 1.0f : 0.0f;

        const int semI = ssem[bi];
        const int p = y * W_OUT + px;
        out[p]            = (float)(smaskid[bi] + 1);
        out[NPIX + p]     = (float)semI;
        out[2 * NPIX + p] = (semI < 80)  ? cf : 0.0f;
        out[3 * NPIX + p] = (semI >= 80) ? cf : 0.0f;
    } else {
        // ---------------- GENERAL PATH (bias-masked, proven) ----------------
        const ull* pa = (const ull*)(sbuf + (x0 - cb) * STRIDE);
        const ull* pb = (const ull*)(sbuf + (x1 - cb) * STRIDE);
        const ull* pg = (const ull*)sbias;

        float fm = -FLT_MAX, bv = -FLT_MAX, s = 0.0f;
        int bi = 0;
        #pragma unroll 8
        for (int c2 = 0; c2 < 64; ++c2) {
            float a0, a1, b0, b1, gg0, gg1;
            f2x2_unpack(pa[c2], a0, a1);
            f2x2_unpack(pb[c2], b0, b1);
            f2x2_unpack(pg[c2], gg0, gg1);
            {
                float v = a0 * omwx + b0 * wx;
                fm = fmaxf(fm, v);
                float mv = v + gg0;
                if (mv > bv) { bv = mv; bi = 2 * c2; }
                float e; EX2(e, mv); s += e;
            }
            {
                float v = a1 * omwx + b1 * wx;
                fm = fmaxf(fm, v);
                float mv = v + gg1;
                if (mv > bv) { bv = mv; bi = 2 * c2 + 1; }
                float e; EX2(e, mv); s += e;
            }
        }
        float eb; EX2(eb, bv);
        const float cf = (s < 2.5f * eb && fm == bv) ? 1.0f : 0.0f;

        float maskid, sem, thing, stuff;
        if (hasdet) {
            const int semI = ssem[bi];
            maskid = (float)(smaskid[bi] + 1);
            sem    = (float)semI;
            thing  = (semI < 80)  ? cf : 0.0f;
            stuff  = (semI >= 80) ? cf : 0.0f;
        } else {
            maskid = 1.0f; sem = 0.0f; thing = 0.0f; stuff = 0.0f;
        }
        const int p = y * W_OUT + px;
        out[p]            = maskid;
        out[NPIX + p]     = sem;
        out[2 * NPIX + p] = thing;
        out[3 * NPIX + p] = stuff;
    }
}

// ---------------------------------------------------------------------------
extern "C" void kernel_launch(void* const* d_in, const int* in_sizes, int n_in,
                              void* d_out, int out_size) {
    const float* logits = (const float*)d_in[0];  // (161,161,128)
    const float* probs  = (const float*)d_in[1];  // (128,134)
    if (n_in >= 2 && in_sizes[0] < in_sizes[1]) { // safety: order by size
        const float* t = logits; logits = probs; probs = t;
    }
    float* out = (float*)d_out;

    classify_kernel<<<1, 1024>>>(probs);
    postproc_kernel<<<dim3(3, H_OUT), 256>>>(logits, out);
}